// round 3
// baseline (speedup 1.0000x reference)
#include <cuda_runtime.h>
#include <cstdint>

// out = joints @ R + t, R = RX(roll) @ RY(pitch) @ RZ(yaw)

struct Rot {
    float r00, r01, r02;
    float r10, r11, r12;
    float r20, r21, r22;
    float tx, ty, tz;
};

__device__ __forceinline__ Rot make_rot(const float* __restrict__ ori,
                                        const float* __restrict__ trs) {
    float sr, cr, sp, cp, sy, cy;
    sincosf(ori[0], &sr, &cr);
    sincosf(ori[1], &sp, &cp);
    sincosf(ori[2], &sy, &cy);
    Rot R;
    R.r00 = cp * cy;                R.r01 = -cp * sy;               R.r02 = sp;
    R.r10 = cr * sy + sr * sp * cy; R.r11 = cr * cy - sr * sp * sy; R.r12 = -sr * cp;
    R.r20 = sr * sy - cr * sp * cy; R.r21 = sr * cy + cr * sp * sy; R.r22 = cr * cp;
    R.tx = trs[0]; R.ty = trs[1]; R.tz = trs[2];
    return R;
}

__device__ __forceinline__ void xform(const Rot& R, float x, float y, float z,
                                      float& ox, float& oy, float& oz) {
    ox = fmaf(x, R.r00, fmaf(y, R.r10, fmaf(z, R.r20, R.tx)));
    oy = fmaf(x, R.r01, fmaf(y, R.r11, fmaf(z, R.r21, R.ty)));
    oz = fmaf(x, R.r02, fmaf(y, R.r12, fmaf(z, R.r22, R.tz)));
}

__device__ __forceinline__ uint32_t smem_u32(const void* p) {
    uint32_t a;
    asm("{ .reg .u64 t; cvta.to.shared.u64 t, %1; cvt.u32.u64 %0, t; }"
        : "=r"(a) : "l"(p));
    return a;
}

// Transform 3 consecutive float4s (4 points) held in registers.
__device__ __forceinline__ void xform12(const Rot& R, float4& a, float4& b, float4& c) {
    float4 oa, ob, oc;
    xform(R, a.x, a.y, a.z, oa.x, oa.y, oa.z);
    xform(R, a.w, b.x, b.y, oa.w, ob.x, ob.y);
    xform(R, b.z, b.w, c.x, ob.z, ob.w, oc.x);
    xform(R, c.y, c.z, c.w, oc.y, oc.z, oc.w);
    a = oa; b = ob; c = oc;
}

// One block = one 24KB tile (1536 float4 = 2048 points). Bulk-async in, smem
// transform in place, bulk-async out. 256 threads, each owns 6 float4s.
static constexpr int TILE_F4    = 1536;
static constexpr int TILE_BYTES = TILE_F4 * 16;  // 24576

__global__ void __launch_bounds__(256)
transform_tma(const float* __restrict__ in, float* __restrict__ out,
              const float* __restrict__ ori, const float* __restrict__ trs) {
    __shared__ __align__(16) float4 s[TILE_F4];
    __shared__ __align__(8) uint64_t mbar;

    const int t = threadIdx.x;
    const uint32_t s_addr = smem_u32(s);
    const uint32_t m_addr = smem_u32(&mbar);
    const char* gsrc = (const char*)in  + (long)blockIdx.x * TILE_BYTES;
    char*       gdst = (char*)out       + (long)blockIdx.x * TILE_BYTES;

    if (t == 0) {
        asm volatile("mbarrier.init.shared.b64 [%0], 1;" :: "r"(m_addr) : "memory");
    }
    __syncthreads();

    if (t == 0) {
        asm volatile("mbarrier.arrive.expect_tx.shared.b64 _, [%0], %1;"
                     :: "r"(m_addr), "r"(TILE_BYTES) : "memory");
        asm volatile("cp.async.bulk.shared::cta.global.mbarrier::complete_tx::bytes "
                     "[%0], [%1], %2, [%3];"
                     :: "r"(s_addr), "l"(gsrc), "r"(TILE_BYTES), "r"(m_addr)
                     : "memory");
    }

    // Rotation matrix overlaps the bulk load (MUFU, independent).
    Rot R = make_rot(ori, trs);

    // Wait for TMA completion (phase 0).
    {
        uint32_t done;
        asm volatile(
            "{\n\t.reg .pred p;\n\t"
            "mbarrier.try_wait.parity.acquire.cta.shared::cta.b64 p, [%1], 0;\n\t"
            "selp.b32 %0, 1, 0, p;\n\t}"
            : "=r"(done) : "r"(m_addr) : "memory");
        if (!done) {
            asm volatile(
                "{\n\t.reg .pred P1;\n\t"
                "W%=:\n\t"
                "mbarrier.try_wait.parity.acquire.cta.shared::cta.b64 P1, [%0], 0, 0x989680;\n\t"
                "@P1 bra.uni D%=;\n\t"
                "bra.uni W%=;\n\t"
                "D%=:\n\t}"
                :: "r"(m_addr) : "memory");
        }
    }

    // Each thread: two groups of 3 consecutive float4s (48B stride -> no bank
    // conflicts on LDS.128/STS.128). In-place transform.
    {
        float4 a = s[3 * t + 0], b = s[3 * t + 1], c = s[3 * t + 2];
        float4 d = s[768 + 3 * t + 0], e = s[768 + 3 * t + 1], f = s[768 + 3 * t + 2];
        xform12(R, a, b, c);
        xform12(R, d, e, f);
        s[3 * t + 0] = a; s[3 * t + 1] = b; s[3 * t + 2] = c;
        s[768 + 3 * t + 0] = d; s[768 + 3 * t + 1] = e; s[768 + 3 * t + 2] = f;
    }
    __syncthreads();

    if (t == 0) {
        asm volatile("fence.proxy.async.shared::cta;" ::: "memory");
        asm volatile("cp.async.bulk.global.shared::cta.bulk_group [%0], [%1], %2;"
                     :: "l"(gdst), "r"(s_addr), "r"(TILE_BYTES) : "memory");
        asm volatile("cp.async.bulk.commit_group;" ::: "memory");
        asm volatile("cp.async.bulk.wait_group 0;" ::: "memory");
        asm volatile("mbarrier.inval.shared.b64 [%0];" :: "r"(m_addr) : "memory");
    }
}

// Scalar tail: one thread per remaining point.
__global__ void transform_tail(const float* __restrict__ in, float* __restrict__ out,
                               const float* __restrict__ ori, const float* __restrict__ trs,
                               int start_pt, int n_pts) {
    int p = start_pt + blockIdx.x * blockDim.x + threadIdx.x;
    if (p >= n_pts) return;
    Rot R = make_rot(ori, trs);
    long o = 3L * p;
    float x = in[o], y = in[o + 1], z = in[o + 2];
    float ox, oy, oz;
    xform(R, x, y, z, ox, oy, oz);
    out[o] = ox; out[o + 1] = oy; out[o + 2] = oz;
}

extern "C" void kernel_launch(void* const* d_in, const int* in_sizes, int n_in,
                              void* d_out, int out_size) {
    const float* joints = (const float*)d_in[0];
    const float* ori    = (const float*)d_in[1];
    const float* trs    = (const float*)d_in[2];
    float* out = (float*)d_out;

    const int n_floats = in_sizes[0];
    const int n_points = n_floats / 3;

    const int tiles = n_floats / (TILE_F4 * 4);   // floats per tile = 6144
    if (tiles > 0) {
        transform_tma<<<tiles, 256>>>(joints, out, ori, trs);
    }
    const int done_pts = tiles * (TILE_F4 * 4) / 3;  // 2048 points per tile
    const int tail = n_points - done_pts;
    if (tail > 0) {
        int blocks = (tail + 255) / 256;
        transform_tail<<<blocks, 256>>>(joints, out, ori, trs, done_pts, n_points);
    }
}